// round 11
// baseline (speedup 1.0000x reference)
#include <cuda_runtime.h>
#include <cuda_fp16.h>
#include <cstdint>

// ---------------------------------------------------------------------------
// QuadraticAttentionModule via fp16 mma.sync.m16n8k16.
//   out[b,o] = bias[o] + sum_k X[b,k] * W[o,k]
//   X[b,k] = xf[b,k] (k<1024) else xf[b,i]*xf[b,j]
// GEMM: M=o(1024), N=b(64), K=525824. X pre-materialized as fp16.
// R11: warp-specialized producer/consumer with a 4-slot mbarrier ring.
//   warps 0-7  : consumers (ldmatrix + mma, layout identical to R9)
//   warps 8-11 : producers (W: LDG.128 fp32 -> cvt -> STS fp16; X: cp.async)
// ---------------------------------------------------------------------------

#define IN_DIM 1024
#define NB     64
#define NOUT   1024
#define KTOT   525824
#define KT     64
#define STAGES (KTOT / KT)       // 8216
#define KS     38                // 8*38 = 304 CTAs = 2/SM
#define MT     8
#define SPLIT_Q (STAGES / KS)    // 216
#define SPLIT_R (STAGES % KS)    // 8

#define WSTR     72              // halves per smem row (64 + 8 pad), 144B
#define W_TILE_B (128 * WSTR * 2)   // 18432 B
#define X_TILE_B (64 * WSTR * 2)    //  9216 B
#define SLOT_B   (W_TILE_B + X_TILE_B)   // 27648 B
#define NSLOT    4
#define SMEM_BYTES (1024 + NSLOT * SLOT_B)   // 111616 B (x2 CTA = 223232 <= 228K)

// Scratch (__device__ globals per allocation rules)
__device__ int    d_ij[KTOT];
__device__ __align__(16) __half d_Xh[(size_t)NB * KTOT];   // [b][k] fp16 RN
__device__ float  d_partial[(size_t)KS * NOUT * NB];       // [split][o][b]

// --------------------------- PTX helpers ------------------------------------

__device__ __forceinline__ uint32_t smem_u32(const void* p) {
    uint32_t a;
    asm("{ .reg .u64 t; cvta.to.shared.u64 t, %1; cvt.u32.u64 %0, t; }" : "=r"(a) : "l"(p));
    return a;
}
__device__ __forceinline__ void mbar_init(uint32_t mbar, uint32_t cnt) {
    asm volatile("mbarrier.init.shared.b64 [%0], %1;" :: "r"(mbar), "r"(cnt) : "memory");
}
__device__ __forceinline__ void mbar_arrive(uint32_t mbar) {
    asm volatile("mbarrier.arrive.shared.b64 _, [%0];" :: "r"(mbar) : "memory");
}
__device__ __forceinline__ void mbar_wait(uint32_t mbar, uint32_t parity) {
    asm volatile("{\n\t.reg .pred P;\n\tWL_%=:\n\t"
        "mbarrier.try_wait.parity.acquire.cta.shared::cta.b64 P, [%0], %1, 0x989680;\n\t"
        "@P bra.uni WD_%=;\n\tbra.uni WL_%=;\n\tWD_%=:\n\t}"
        :: "r"(mbar), "r"(parity) : "memory");
}
__device__ __forceinline__ void cp16(uint32_t saddr, const void* gptr) {
    asm volatile("cp.async.cg.shared.global [%0], [%1], 16;"
                 :: "r"(saddr), "l"(gptr) : "memory");
}
__device__ __forceinline__ void cp_arrive(uint32_t mbar) {
    asm volatile("cp.async.mbarrier.arrive.noinc.shared::cta.b64 [%0];"
                 :: "r"(mbar) : "memory");
}
__device__ __forceinline__ void ldsm4(uint32_t* r, uint32_t addr) {
    asm volatile("ldmatrix.sync.aligned.m8n8.x4.shared.b16 {%0,%1,%2,%3}, [%4];"
                 : "=r"(r[0]), "=r"(r[1]), "=r"(r[2]), "=r"(r[3]) : "r"(addr));
}
__device__ __forceinline__ void mma16816(float* d, const uint32_t* a, const uint32_t* b) {
    asm volatile(
        "mma.sync.aligned.m16n8k16.row.col.f32.f16.f16.f32 "
        "{%0,%1,%2,%3}, {%4,%5,%6,%7}, {%8,%9}, {%0,%1,%2,%3};\n"
        : "+f"(d[0]), "+f"(d[1]), "+f"(d[2]), "+f"(d[3])
        : "r"(a[0]), "r"(a[1]), "r"(a[2]), "r"(a[3]), "r"(b[0]), "r"(b[1]));
}
// Pack two fp32 -> one u32 of two rn-rounded fp16 (lo = a, hi = b).
__device__ __forceinline__ uint32_t packh2(float a, float b) {
    uint32_t r;
    asm("cvt.rn.f16x2.f32 %0, %2, %1;" : "=r"(r) : "f"(a), "f"(b));
    return r;
}

// --------------------------- prep kernels ----------------------------------

__device__ __forceinline__ long long triu_off(long long i) {
    return i * IN_DIM - i * (i - 1) / 2;
}

__global__ void qa_ij() {
    int k = blockIdx.x * blockDim.x + threadIdx.x;
    if (k >= KTOT) return;
    if (k < IN_DIM) { d_ij[k] = (k << 16) | 0xFFFF; return; }
    long long p = k - IN_DIM;
    double nn = 2.0 * IN_DIM + 1.0;
    int i = (int)((nn - sqrt(nn * nn - 8.0 * (double)p)) * 0.5);
    if (i < 0) i = 0;
    if (i > IN_DIM - 1) i = IN_DIM - 1;
    while (i > 0 && triu_off(i) > p) --i;
    while (i < IN_DIM - 1 && triu_off(i + 1) <= p) ++i;
    int j = i + (int)(p - triu_off(i));
    d_ij[k] = (i << 16) | j;
}

// Materialize X[b][k] in fp16 (round-to-nearest).
__global__ void qa_buildXh(const float* __restrict__ in) {
    int k = blockIdx.x * 256 + threadIdx.x;    // grid.x = KTOT/256 = 2054
    int b = blockIdx.y;
    int ij = d_ij[k];
    int i = ij >> 16, j = ij & 0xFFFF;
    float v = in[b * IN_DIM + i];
    if (j != 0xFFFF) v *= in[b * IN_DIM + j];
    d_Xh[(size_t)b * KTOT + k] = __float2half_rn(v);
}

// --------------------------- main GEMM -------------------------------------
// SMEM: [0,32)   full[4] mbarriers (count 256 = 128 STS-arrive + 128 cp-arrive)
//       [64,96)  empty[4] mbarriers (count 256 = consumer threads)
//       [1024 + slot*27648)  W fp16 [128][72] then X fp16 [64][72]

__global__ __launch_bounds__(384, 2)
void qa_main(const float* __restrict__ W) {
    extern __shared__ __align__(128) char smem[];
    const uint32_t sb = smem_u32(smem);
    const int tid = threadIdx.x, lane = tid & 31, wid = tid >> 5;

    const int o_base = blockIdx.x * 128;
    const int split  = blockIdx.y;
    const int s0 = split * SPLIT_Q + min(split, SPLIT_R);
    const int s1 = s0 + SPLIT_Q + (split < SPLIT_R ? 1 : 0);

    if (tid == 0) {
        #pragma unroll
        for (int i = 0; i < NSLOT; i++) {
            mbar_init(sb + i * 8, 256);        // full
            mbar_init(sb + 64 + i * 8, 256);   // empty
        }
    }
    __syncthreads();

    if (wid >= 8) {
        // ================= producers (warps 8-11, pt = 0..127) ==============
        const int pt  = tid - 256;
        const int pr0 = pt >> 4, pc = pt & 15;     // W: 16 lanes span one 256B row
        const float* wptr = W + (size_t)(o_base + pr0) * KTOT
                              + (size_t)s0 * KT + pc * 4;
        const uint32_t wsto = pr0 * 144 + pc * 8;  // fp16 dst (+8j*144 per row step)
        const int xr = pt >> 1, xh = pt & 1;       // X: 2 lanes span one 128B row
        const __half* xptr = d_Xh + (size_t)xr * KTOT + (size_t)s0 * KT + xh * 32;
        const uint32_t xsto = (uint32_t)W_TILE_B + xr * 144 + xh * 64;

        float4 ra[8];
        auto loadWb = [&](int s, int bt) {         // rows pr0 + 8j (+64 if bt)
            const float* p = wptr + (size_t)(s - s0) * KT
                                  + (size_t)(bt ? 64 : 0) * KTOT;
            #pragma unroll
            for (int j = 0; j < 8; j++)
                ra[j] = *(const float4*)(p + (size_t)(8 * j) * KTOT);
        };
        auto storeWb = [&](int slot, int bt) {
            char* base = smem + 1024 + slot * SLOT_B + wsto + (bt ? 64 * 144 : 0);
            #pragma unroll
            for (int j = 0; j < 8; j++) {
                uint2 u;
                u.x = packh2(ra[j].x, ra[j].y);
                u.y = packh2(ra[j].z, ra[j].w);
                *(uint2*)(base + j * 8 * 144) = u;   // STS.64, conflict-free
            }
        };

        int slot = 0, ph = 1;                      // fresh barrier: parity-1 passes
        loadWb(s0, 0);                             // prologue prefetch
        for (int s = s0; s < s1; s++) {
            mbar_wait(sb + 64 + slot * 8, (uint32_t)ph);
            const uint32_t tb = sb + 1024 + slot * SLOT_B;
            const __half* xp = xptr + (size_t)(s - s0) * KT;
            #pragma unroll
            for (int c = 0; c < 4; c++)
                cp16(tb + xsto + c * 16, xp + c * 8);
            cp_arrive(sb + slot * 8);              // X completion -> full
            storeWb(slot, 0);                      // batch0 loaded >= 1 stage ago
            loadWb(s, 1);
            storeWb(slot, 1);                      // one exposed-latency stall, OK
            if (s + 1 < s1) loadWb(s + 1, 0);      // next stage's batch0 in flight
            mbar_arrive(sb + slot * 8);            // W done -> full
            if (++slot == NSLOT) { slot = 0; ph ^= 1; }
        }
    } else {
        // ================= consumers (warps 0-7) ============================
        const int warpM = wid >> 2, warpN = wid & 3;
        const uint32_t aoff = ((warpM * 64 + (lane & 15)) * WSTR + ((lane >> 4) * 8)) * 2;
        const uint32_t boff = ((warpN * 16 + ((lane >> 4) * 8) + (lane & 7)) * WSTR
                              + (((lane >> 3) & 1) * 8)) * 2;

        float acc[4][2][4];
        #pragma unroll
        for (int mt = 0; mt < 4; mt++)
            #pragma unroll
            for (int nt = 0; nt < 2; nt++)
                #pragma unroll
                for (int r = 0; r < 4; r++) acc[mt][nt][r] = 0.f;

        int slot = 0, ph = 0;
        for (int s = s0; s < s1; s++) {
            mbar_wait(sb + slot * 8, (uint32_t)ph);
            const uint32_t wbase = sb + 1024 + slot * SLOT_B;
            const uint32_t xbase = wbase + W_TILE_B;
            #pragma unroll
            for (int ks = 0; ks < 4; ks++) {
                const int kk = ks * 16;
                uint32_t a[4][4], b4[4];
                #pragma unroll
                for (int mt = 0; mt < 4; mt++)
                    ldsm4(a[mt], wbase + aoff + (mt * 16 * WSTR + kk) * 2);
                ldsm4(b4, xbase + boff + kk * 2);
                #pragma unroll
                for (int mt = 0; mt < 4; mt++)
                    #pragma unroll
                    for (int nt = 0; nt < 2; nt++)
                        mma16816(acc[mt][nt], a[mt], b4 + nt * 2);
            }
            mbar_arrive(sb + 64 + slot * 8);       // slot free
            if (++slot == NSLOT) { slot = 0; ph ^= 1; }
        }

        // Epilogue: partial[split][o][b], vectorized float2
        float* part = d_partial + (size_t)split * (NOUT * NB);
        #pragma unroll
        for (int mt = 0; mt < 4; mt++)
            #pragma unroll
            for (int nt = 0; nt < 2; nt++) {
                int o  = o_base + warpM * 64 + mt * 16 + (lane >> 2);
                int bb = warpN * 16 + nt * 8 + 2 * (lane & 3);
                *(float2*)&part[(size_t)o * NB + bb] =
                    make_float2(acc[mt][nt][0], acc[mt][nt][1]);
                *(float2*)&part[(size_t)(o + 8) * NB + bb] =
                    make_float2(acc[mt][nt][2], acc[mt][nt][3]);
            }
    }
}

// --------------------------- reduce ----------------------------------------

__global__ void qa_reduce(const float* __restrict__ bias, float* __restrict__ out) {
    int t = blockIdx.x * blockDim.x + threadIdx.x;  // t = o*64 + b
    int o = t >> 6, b = t & 63;
    float s = bias[o];
    #pragma unroll
    for (int k = 0; k < KS; k++)
        s += d_partial[(size_t)k * (NOUT * NB) + t];   // coalesced reads
    out[(size_t)b * NOUT + o] = s;                     // scattered 4B writes
}

// --------------------------- launch ----------------------------------------

extern "C" void kernel_launch(void* const* d_in, const int* in_sizes, int n_in,
                              void* d_out, int out_size) {
    const float* input_ = (const float*)d_in[0];   // (64,32,32) fp32
    const float* W      = (const float*)d_in[1];   // (1024, 525824) fp32
    const float* bias   = (const float*)d_in[2];   // (1024,) fp32
    float* out = (float*)d_out;                    // (64,32,32) fp32

    cudaFuncSetAttribute(qa_main, cudaFuncAttributeMaxDynamicSharedMemorySize, SMEM_BYTES);

    qa_ij<<<(KTOT + 1023) / 1024, 1024>>>();
    qa_buildXh<<<dim3(KTOT / 256, NB), 256>>>(input_);
    qa_main<<<dim3(MT, KS), 384, SMEM_BYTES>>>(W);
    qa_reduce<<<64, 1024>>>(bias, out);
}